// round 3
// baseline (speedup 1.0000x reference)
#include <cuda_runtime.h>
#include <math.h>

#define IMG_H 200
#define IMG_W 200
#define IMG_C 256
#define C4 (IMG_C / 4)   // 64 float4 per pixel

// Warp-per-task: each task = one (roi, cell, channel-half). 4 float4 loads per
// thread, 1 float4 store. Low regs -> high occupancy; flat grid -> no tail.
__global__ __launch_bounds__(256) void roipool_kernel(
        const float* __restrict__ img,
        const float* __restrict__ rois,
        float* __restrict__ out,
        int ps, int n_tasks) {
    const int warp = threadIdx.x >> 5;
    const int lane = threadIdx.x & 31;
    const int gw   = blockIdx.x * 8 + warp;   // global warp id
    if (gw >= n_tasks) return;

    const int pp      = ps * ps;
    const int cell_id = gw >> 1;              // (roi, cell)
    const int half    = gw & 1;               // channel half
    const int r       = cell_id / pp;
    const int cell    = cell_id - r * pp;
    const int py      = cell / ps;
    const int px      = cell - py * ps;

    // RoI: [x, y, w, h] float -> int (matches rois.astype(int32))
    const float4 rv = reinterpret_cast<const float4*>(rois)[r];
    const int x = (int)rv.x;
    const int y = (int)rv.y;
    const int w = (int)rv.z;
    const int h = (int)rv.w;

    const float sy = (float)h / (float)ps;
    const float sx = (float)w / (float)ps;
    const float src_y = (float)py * sy;
    const float src_x = (float)px * sx;
    const int y0 = (int)floorf(src_y);
    const int x0 = (int)floorf(src_x);
    const float wy = src_y - (float)y0;
    const float wx = src_x - (float)x0;

    const int gy0 = min(max(y + min(max(y0,     0), h - 1), 0), IMG_H - 1);
    const int gy1 = min(max(y + min(max(y0 + 1, 0), h - 1), 0), IMG_H - 1);
    const int gx0 = min(max(x + min(max(x0,     0), w - 1), 0), IMG_W - 1);
    const int gx1 = min(max(x + min(max(x0 + 1, 0), w - 1), 0), IMG_W - 1);

    const float4* __restrict__ f4 = reinterpret_cast<const float4*>(img);
    const int c = half * 32 + lane;           // float4-channel index 0..63

    // 4 independent 16B loads
    const float4 v00 = f4[(size_t)(gy0 * IMG_W + gx0) * C4 + c];
    const float4 v01 = f4[(size_t)(gy0 * IMG_W + gx1) * C4 + c];
    const float4 v10 = f4[(size_t)(gy1 * IMG_W + gx0) * C4 + c];
    const float4 v11 = f4[(size_t)(gy1 * IMG_W + gx1) * C4 + c];

    const float omwx = 1.0f - wx;
    const float omwy = 1.0f - wy;

    float4 res;
    {
        float t, b;
        t = v00.x * omwx + v01.x * wx; b = v10.x * omwx + v11.x * wx; res.x = t * omwy + b * wy;
        t = v00.y * omwx + v01.y * wx; b = v10.y * omwx + v11.y * wx; res.y = t * omwy + b * wy;
        t = v00.z * omwx + v01.z * wx; b = v10.z * omwx + v11.z * wx; res.z = t * omwy + b * wy;
        t = v00.w * omwx + v01.w * wx; b = v10.w * omwx + v11.w * wx; res.w = t * omwy + b * wy;
    }

    // Evict-first store: don't let the 100MB output stream evict the image in L2.
    __stcs(reinterpret_cast<float4*>(out) + (size_t)cell_id * C4 + c, res);
}

extern "C" void kernel_launch(void* const* d_in, const int* in_sizes, int n_in,
                              void* d_out, int out_size) {
    const float* img  = (const float*)d_in[0];
    const float* rois = (const float*)d_in[1];
    float* out = (float*)d_out;

    const int n_rois = in_sizes[1] / 4;
    const int pp = out_size / (n_rois * IMG_C);
    int ps = (int)(sqrtf((float)pp) + 0.5f);
    if (ps < 1) ps = 1;

    const int n_tasks = n_rois * ps * ps * 2;      // warp tasks (2 halves/cell)
    const int blocks  = (n_tasks + 7) / 8;         // 8 warps per CTA
    roipool_kernel<<<blocks, 256>>>(img, rois, out, ps, n_tasks);
}

// round 4
// speedup vs baseline: 1.1637x; 1.1637x over previous
#include <cuda_runtime.h>
#include <math.h>

#define IMG_H 200
#define IMG_W 200
#define IMG_C 256
#define C4 (IMG_C / 4)   // 64 float4 per pixel
#define MAX_PP 64        // supports ps up to 8

struct CellGeom {
    int o00, o01, o10, o11;   // pixel offsets (y*W+x)
    float wx, wy;
};

// One CTA (256 thr) per RoI. Cell geometry computed once into smem, then 8
// warps stream 2*pp (cell, channel-half) tasks: 4 float4 loads, blend, store.
__global__ __launch_bounds__(256) void roipool_kernel(
        const float* __restrict__ img,
        const float* __restrict__ rois,
        float* __restrict__ out,
        int ps) {
    __shared__ CellGeom geom[MAX_PP];

    const int r    = blockIdx.x;
    const int warp = threadIdx.x >> 5;
    const int lane = threadIdx.x & 31;
    const int pp   = ps * ps;

    // RoI: [x, y, w, h] float -> int (matches rois.astype(int32))
    const float4 rv = reinterpret_cast<const float4*>(rois)[r];
    const int x = (int)rv.x;
    const int y = (int)rv.y;
    const int w = (int)rv.z;
    const int h = (int)rv.w;

    // --- geometry precompute: one thread per cell ---
    if (threadIdx.x < pp) {
        const int cell = threadIdx.x;
        const int py = cell / ps;
        const int px = cell - py * ps;

        const float sy = (float)h / (float)ps;
        const float sx = (float)w / (float)ps;
        const float src_y = (float)py * sy;
        const float src_x = (float)px * sx;
        const int y0 = (int)floorf(src_y);
        const int x0 = (int)floorf(src_x);

        const int gy0 = min(max(y + min(max(y0,     0), h - 1), 0), IMG_H - 1);
        const int gy1 = min(max(y + min(max(y0 + 1, 0), h - 1), 0), IMG_H - 1);
        const int gx0 = min(max(x + min(max(x0,     0), w - 1), 0), IMG_W - 1);
        const int gx1 = min(max(x + min(max(x0 + 1, 0), w - 1), 0), IMG_W - 1);

        CellGeom g;
        g.o00 = gy0 * IMG_W + gx0;
        g.o01 = gy0 * IMG_W + gx1;
        g.o10 = gy1 * IMG_W + gx0;
        g.o11 = gy1 * IMG_W + gx1;
        g.wx  = src_x - (float)x0;
        g.wy  = src_y - (float)y0;
        geom[cell] = g;
    }
    __syncthreads();

    const float4* __restrict__ f4 = reinterpret_cast<const float4*>(img);
    float4* __restrict__ o4 = reinterpret_cast<float4*>(out) + (size_t)r * pp * C4;

    const int n_tasks = pp * 2;
    for (int task = warp; task < n_tasks; task += 8) {
        const int cell = task >> 1;
        const int c    = ((task & 1) << 5) + lane;   // float4-channel 0..63

        const CellGeom g = geom[cell];               // broadcast LDS

        const float4 v00 = f4[(size_t)g.o00 * C4 + c];
        const float4 v01 = f4[(size_t)g.o01 * C4 + c];
        const float4 v10 = f4[(size_t)g.o10 * C4 + c];
        const float4 v11 = f4[(size_t)g.o11 * C4 + c];

        const float wx = g.wx, wy = g.wy;
        const float omwx = 1.0f - wx;
        const float omwy = 1.0f - wy;

        float4 res;
        {
            float t, b;
            t = v00.x * omwx + v01.x * wx; b = v10.x * omwx + v11.x * wx; res.x = t * omwy + b * wy;
            t = v00.y * omwx + v01.y * wx; b = v10.y * omwx + v11.y * wx; res.y = t * omwy + b * wy;
            t = v00.z * omwx + v01.z * wx; b = v10.z * omwx + v11.z * wx; res.z = t * omwy + b * wy;
            t = v00.w * omwx + v01.w * wx; b = v10.w * omwx + v11.w * wx; res.w = t * omwy + b * wy;
        }

        o4[(size_t)cell * C4 + c] = res;
    }
}

extern "C" void kernel_launch(void* const* d_in, const int* in_sizes, int n_in,
                              void* d_out, int out_size) {
    const float* img  = (const float*)d_in[0];
    const float* rois = (const float*)d_in[1];
    float* out = (float*)d_out;

    const int n_rois = in_sizes[1] / 4;
    const int pp = out_size / (n_rois * IMG_C);
    int ps = (int)(sqrtf((float)pp) + 0.5f);
    if (ps < 1) ps = 1;
    if (ps * ps > MAX_PP) ps = 8;

    roipool_kernel<<<n_rois, 256>>>(img, rois, out, ps);
}

// round 5
// speedup vs baseline: 1.2502x; 1.0744x over previous
#include <cuda_runtime.h>
#include <math.h>

#define IMG_H 200
#define IMG_W 200
#define IMG_C 256
#define C4 (IMG_C / 4)   // 64 float4 per pixel
#define MAX_PP 64        // supports ps up to 8

struct CellGeom {
    int o00, o01, o10, o11;   // pixel offsets (y*W+x)
    float wx, wy;
};

// One CTA (256 thr) per RoI. Geometry once into smem; 8 warps stream 2*pp
// (cell, channel-half) tasks with register double-buffering: next task's 4
// float4 loads are issued before the current task's blend+store -> MLP 8.
__global__ __launch_bounds__(256) void roipool_kernel(
        const float* __restrict__ img,
        const float* __restrict__ rois,
        float* __restrict__ out,
        int ps) {
    __shared__ CellGeom geom[MAX_PP];

    const int r    = blockIdx.x;
    const int warp = threadIdx.x >> 5;
    const int lane = threadIdx.x & 31;
    const int pp   = ps * ps;

    const float4 rv = reinterpret_cast<const float4*>(rois)[r];
    const int x = (int)rv.x;
    const int y = (int)rv.y;
    const int w = (int)rv.z;
    const int h = (int)rv.w;

    if (threadIdx.x < pp) {
        const int cell = threadIdx.x;
        const int py = cell / ps;
        const int px = cell - py * ps;

        const float sy = (float)h / (float)ps;
        const float sx = (float)w / (float)ps;
        const float src_y = (float)py * sy;
        const float src_x = (float)px * sx;
        const int y0 = (int)floorf(src_y);
        const int x0 = (int)floorf(src_x);

        const int gy0 = min(max(y + min(max(y0,     0), h - 1), 0), IMG_H - 1);
        const int gy1 = min(max(y + min(max(y0 + 1, 0), h - 1), 0), IMG_H - 1);
        const int gx0 = min(max(x + min(max(x0,     0), w - 1), 0), IMG_W - 1);
        const int gx1 = min(max(x + min(max(x0 + 1, 0), w - 1), 0), IMG_W - 1);

        CellGeom g;
        g.o00 = gy0 * IMG_W + gx0;
        g.o01 = gy0 * IMG_W + gx1;
        g.o10 = gy1 * IMG_W + gx0;
        g.o11 = gy1 * IMG_W + gx1;
        g.wx  = src_x - (float)x0;
        g.wy  = src_y - (float)y0;
        geom[cell] = g;
    }
    __syncthreads();

    const float4* __restrict__ f4 = reinterpret_cast<const float4*>(img);
    float4* __restrict__ o4 = reinterpret_cast<float4*>(out) + (size_t)r * pp * C4;

    const int n_tasks = pp * 2;
    int task = warp;
    if (task >= n_tasks) return;

    // ---- prologue: issue loads for first task ----
    int cell = task >> 1;
    int c    = ((task & 1) << 5) + lane;
    CellGeom g = geom[cell];
    float4 v00 = f4[(size_t)g.o00 * C4 + c];
    float4 v01 = f4[(size_t)g.o01 * C4 + c];
    float4 v10 = f4[(size_t)g.o10 * C4 + c];
    float4 v11 = f4[(size_t)g.o11 * C4 + c];
    float wx = g.wx, wy = g.wy;

    for (;;) {
        const int next = task + 8;
        const bool have_next = next < n_tasks;
        const int nt = have_next ? next : task;   // clamp: safe re-load of current

        // ---- issue next task's loads (before consuming current) ----
        const int ncell = nt >> 1;
        const int nc    = ((nt & 1) << 5) + lane;
        const CellGeom ng = geom[ncell];
        const float4 n00 = f4[(size_t)ng.o00 * C4 + nc];
        const float4 n01 = f4[(size_t)ng.o01 * C4 + nc];
        const float4 n10 = f4[(size_t)ng.o10 * C4 + nc];
        const float4 n11 = f4[(size_t)ng.o11 * C4 + nc];

        // ---- consume current task ----
        const float omwx = 1.0f - wx;
        const float omwy = 1.0f - wy;
        float4 res;
        {
            float t, b;
            t = v00.x * omwx + v01.x * wx; b = v10.x * omwx + v11.x * wx; res.x = t * omwy + b * wy;
            t = v00.y * omwx + v01.y * wx; b = v10.y * omwx + v11.y * wx; res.y = t * omwy + b * wy;
            t = v00.z * omwx + v01.z * wx; b = v10.z * omwx + v11.z * wx; res.z = t * omwy + b * wy;
            t = v00.w * omwx + v01.w * wx; b = v10.w * omwx + v11.w * wx; res.w = t * omwy + b * wy;
        }
        o4[(size_t)cell * C4 + c] = res;

        if (!have_next) break;

        // rotate buffers
        task = next; cell = ncell; c = nc;
        v00 = n00; v01 = n01; v10 = n10; v11 = n11;
        wx = ng.wx; wy = ng.wy;
    }
}

extern "C" void kernel_launch(void* const* d_in, const int* in_sizes, int n_in,
                              void* d_out, int out_size) {
    const float* img  = (const float*)d_in[0];
    const float* rois = (const float*)d_in[1];
    float* out = (float*)d_out;

    const int n_rois = in_sizes[1] / 4;
    const int pp = out_size / (n_rois * IMG_C);
    int ps = (int)(sqrtf((float)pp) + 0.5f);
    if (ps < 1) ps = 1;
    if (ps * ps > MAX_PP) ps = 8;

    roipool_kernel<<<n_rois, 256>>>(img, rois, out, ps);
}

// round 6
// speedup vs baseline: 1.3285x; 1.0626x over previous
#include <cuda_runtime.h>
#include <math.h>

#define IMG_H 200
#define IMG_W 200
#define IMG_C 256
#define C4 (IMG_C / 4)   // 64 float4 per pixel
#define MAX_PP 64        // supports ps up to 8

struct CellGeom {
    int o00, o01, o10, o11;   // pixel offsets (y*W+x)
    float wx, wy;
};

// One CTA (256 thr = 8 warps) per RoI. Geometry once into smem. Each warp
// processes one FULL cell per iteration: 8 independent LDG.128 (channels
// lane and lane+32 for all 4 corners) -> true MLP-8 that ptxas cannot
// serialize, since all 8 results feed the blend. launch_bounds(256,4)
// permits ~60 regs so all 8 float4 stay live.
__global__ __launch_bounds__(256, 4) void roipool_kernel(
        const float* __restrict__ img,
        const float* __restrict__ rois,
        float* __restrict__ out,
        int ps) {
    __shared__ CellGeom geom[MAX_PP];

    const int r    = blockIdx.x;
    const int warp = threadIdx.x >> 5;
    const int lane = threadIdx.x & 31;
    const int pp   = ps * ps;

    const float4 rv = reinterpret_cast<const float4*>(rois)[r];
    const int x = (int)rv.x;
    const int y = (int)rv.y;
    const int w = (int)rv.z;
    const int h = (int)rv.w;

    if (threadIdx.x < pp) {
        const int cell = threadIdx.x;
        const int py = cell / ps;
        const int px = cell - py * ps;

        const float sy = (float)h / (float)ps;
        const float sx = (float)w / (float)ps;
        const float src_y = (float)py * sy;
        const float src_x = (float)px * sx;
        const int y0 = (int)floorf(src_y);
        const int x0 = (int)floorf(src_x);

        const int gy0 = min(max(y + min(max(y0,     0), h - 1), 0), IMG_H - 1);
        const int gy1 = min(max(y + min(max(y0 + 1, 0), h - 1), 0), IMG_H - 1);
        const int gx0 = min(max(x + min(max(x0,     0), w - 1), 0), IMG_W - 1);
        const int gx1 = min(max(x + min(max(x0 + 1, 0), w - 1), 0), IMG_W - 1);

        CellGeom g;
        g.o00 = gy0 * IMG_W + gx0;
        g.o01 = gy0 * IMG_W + gx1;
        g.o10 = gy1 * IMG_W + gx0;
        g.o11 = gy1 * IMG_W + gx1;
        g.wx  = src_x - (float)x0;
        g.wy  = src_y - (float)y0;
        geom[cell] = g;
    }
    __syncthreads();

    const float4* __restrict__ f4 = reinterpret_cast<const float4*>(img);
    float4* __restrict__ o4 = reinterpret_cast<float4*>(out) + (size_t)r * pp * C4;

    const int ca = lane;
    const int cb = lane + 32;

    for (int cell = warp; cell < pp; cell += 8) {
        const CellGeom g = geom[cell];   // broadcast LDS

        const float4* __restrict__ p00 = f4 + (size_t)g.o00 * C4;
        const float4* __restrict__ p01 = f4 + (size_t)g.o01 * C4;
        const float4* __restrict__ p10 = f4 + (size_t)g.o10 * C4;
        const float4* __restrict__ p11 = f4 + (size_t)g.o11 * C4;

        // 8 independent 16B loads -> MLP 8
        const float4 a00 = p00[ca];
        const float4 a01 = p01[ca];
        const float4 a10 = p10[ca];
        const float4 a11 = p11[ca];
        const float4 b00 = p00[cb];
        const float4 b01 = p01[cb];
        const float4 b10 = p10[cb];
        const float4 b11 = p11[cb];

        const float wx = g.wx, wy = g.wy;
        const float omwx = 1.0f - wx;
        const float omwy = 1.0f - wy;

        float4 ra, rb;
        {
            float t, b;
            t = a00.x * omwx + a01.x * wx; b = a10.x * omwx + a11.x * wx; ra.x = t * omwy + b * wy;
            t = a00.y * omwx + a01.y * wx; b = a10.y * omwx + a11.y * wx; ra.y = t * omwy + b * wy;
            t = a00.z * omwx + a01.z * wx; b = a10.z * omwx + a11.z * wx; ra.z = t * omwy + b * wy;
            t = a00.w * omwx + a01.w * wx; b = a10.w * omwx + a11.w * wx; ra.w = t * omwy + b * wy;

            t = b00.x * omwx + b01.x * wx; b = b10.x * omwx + b11.x * wx; rb.x = t * omwy + b * wy;
            t = b00.y * omwx + b01.y * wx; b = b10.y * omwx + b11.y * wx; rb.y = t * omwy + b * wy;
            t = b00.z * omwx + b01.z * wx; b = b10.z * omwx + b11.z * wx; rb.z = t * omwy + b * wy;
            t = b00.w * omwx + b01.w * wx; b = b10.w * omwx + b11.w * wx; rb.w = t * omwy + b * wy;
        }

        float4* __restrict__ oc = o4 + (size_t)cell * C4;
        oc[ca] = ra;
        oc[cb] = rb;
    }
}

extern "C" void kernel_launch(void* const* d_in, const int* in_sizes, int n_in,
                              void* d_out, int out_size) {
    const float* img  = (const float*)d_in[0];
    const float* rois = (const float*)d_in[1];
    float* out = (float*)d_out;

    const int n_rois = in_sizes[1] / 4;
    const int pp = out_size / (n_rois * IMG_C);
    int ps = (int)(sqrtf((float)pp) + 0.5f);
    if (ps < 1) ps = 1;
    if (ps * ps > MAX_PP) ps = 8;

    roipool_kernel<<<n_rois, 256>>>(img, rois, out, ps);
}

// round 7
// speedup vs baseline: 1.4065x; 1.0587x over previous
#include <cuda_runtime.h>
#include <math.h>

#define IMG_H 200
#define IMG_W 200
#define IMG_C 256
#define PIX_BYTES (IMG_C * 4)   // 1024 bytes per pixel
#define MAX_PP 64               // supports ps up to 8

struct CellGeom {
    unsigned o00, o01, o10, o11;  // BYTE offsets of the 4 corner pixels
    float wx, wy;
};

// One CTA (256 thr = 8 warps) per RoI. Geometry once into smem. Each warp does
// one full cell per iteration (8 independent LDG.128 -> MLP 8). Cells with
// wx==0 / wy==0 (always true for row/col 0 with integer RoIs) skip the unused
// corner loads: ~14% fewer load wavefronts, warp-uniform branching.
__global__ __launch_bounds__(256, 5) void roipool_kernel(
        const float* __restrict__ img,
        const float* __restrict__ rois,
        float* __restrict__ out,
        int ps) {
    __shared__ CellGeom geom[MAX_PP];

    const int r    = blockIdx.x;
    const int warp = threadIdx.x >> 5;
    const int lane = threadIdx.x & 31;
    const int pp   = ps * ps;

    const float4 rv = reinterpret_cast<const float4*>(rois)[r];
    const int x = (int)rv.x;
    const int y = (int)rv.y;
    const int w = (int)rv.z;
    const int h = (int)rv.w;

    if (threadIdx.x < pp) {
        const int cell = threadIdx.x;
        const int py = cell / ps;
        const int px = cell - py * ps;

        const float sy = (float)h / (float)ps;
        const float sx = (float)w / (float)ps;
        const float src_y = (float)py * sy;
        const float src_x = (float)px * sx;
        const int y0 = (int)floorf(src_y);
        const int x0 = (int)floorf(src_x);

        const int gy0 = min(max(y + min(max(y0,     0), h - 1), 0), IMG_H - 1);
        const int gy1 = min(max(y + min(max(y0 + 1, 0), h - 1), 0), IMG_H - 1);
        const int gx0 = min(max(x + min(max(x0,     0), w - 1), 0), IMG_W - 1);
        const int gx1 = min(max(x + min(max(x0 + 1, 0), w - 1), 0), IMG_W - 1);

        CellGeom g;
        g.o00 = (unsigned)(gy0 * IMG_W + gx0) * PIX_BYTES;
        g.o01 = (unsigned)(gy0 * IMG_W + gx1) * PIX_BYTES;
        g.o10 = (unsigned)(gy1 * IMG_W + gx0) * PIX_BYTES;
        g.o11 = (unsigned)(gy1 * IMG_W + gx1) * PIX_BYTES;
        g.wx  = src_x - (float)x0;
        g.wy  = src_y - (float)y0;
        geom[cell] = g;
    }
    __syncthreads();

    const char* __restrict__ ib = reinterpret_cast<const char*>(img);
    char* __restrict__ ob = reinterpret_cast<char*>(out)
                          + (unsigned)r * (unsigned)pp * PIX_BYTES;

    const unsigned ca = (unsigned)lane * 16u;   // byte offset of channel-half A
    const unsigned cb = ca + 512u;              // channel-half B

#define LD4(off) (*reinterpret_cast<const float4*>(ib + (off)))

    for (int cell = warp; cell < pp; cell += 8) {
        const CellGeom g = geom[cell];          // broadcast LDS
        char* oc = ob + (unsigned)cell * PIX_BYTES;
        float4* __restrict__ oa = reinterpret_cast<float4*>(oc + ca);
        float4* __restrict__ obp = reinterpret_cast<float4*>(oc + cb);

        const float wx = g.wx, wy = g.wy;
        const bool zx = (wx == 0.0f);
        const bool zy = (wy == 0.0f);

        if (zx && zy) {
            // single corner
            const float4 a00 = LD4(g.o00 + ca);
            const float4 b00 = LD4(g.o00 + cb);
            *oa = a00;
            *obp = b00;
        } else if (zx) {
            // blend in y only: v00, v10
            const float4 a00 = LD4(g.o00 + ca);
            const float4 a10 = LD4(g.o10 + ca);
            const float4 b00 = LD4(g.o00 + cb);
            const float4 b10 = LD4(g.o10 + cb);
            const float omwy = 1.0f - wy;
            float4 ra, rb;
            ra.x = a00.x * omwy + a10.x * wy;
            ra.y = a00.y * omwy + a10.y * wy;
            ra.z = a00.z * omwy + a10.z * wy;
            ra.w = a00.w * omwy + a10.w * wy;
            rb.x = b00.x * omwy + b10.x * wy;
            rb.y = b00.y * omwy + b10.y * wy;
            rb.z = b00.z * omwy + b10.z * wy;
            rb.w = b00.w * omwy + b10.w * wy;
            *oa = ra;
            *obp = rb;
        } else if (zy) {
            // blend in x only: v00, v01
            const float4 a00 = LD4(g.o00 + ca);
            const float4 a01 = LD4(g.o01 + ca);
            const float4 b00 = LD4(g.o00 + cb);
            const float4 b01 = LD4(g.o01 + cb);
            const float omwx = 1.0f - wx;
            float4 ra, rb;
            ra.x = a00.x * omwx + a01.x * wx;
            ra.y = a00.y * omwx + a01.y * wx;
            ra.z = a00.z * omwx + a01.z * wx;
            ra.w = a00.w * omwx + a01.w * wx;
            rb.x = b00.x * omwx + b01.x * wx;
            rb.y = b00.y * omwx + b01.y * wx;
            rb.z = b00.z * omwx + b01.z * wx;
            rb.w = b00.w * omwx + b01.w * wx;
            *oa = ra;
            *obp = rb;
        } else {
            // full bilinear: 8 independent loads (MLP 8)
            const float4 a00 = LD4(g.o00 + ca);
            const float4 a01 = LD4(g.o01 + ca);
            const float4 a10 = LD4(g.o10 + ca);
            const float4 a11 = LD4(g.o11 + ca);
            const float4 b00 = LD4(g.o00 + cb);
            const float4 b01 = LD4(g.o01 + cb);
            const float4 b10 = LD4(g.o10 + cb);
            const float4 b11 = LD4(g.o11 + cb);

            const float omwx = 1.0f - wx;
            const float omwy = 1.0f - wy;
            float4 ra, rb;
            {
                float t, b;
                t = a00.x * omwx + a01.x * wx; b = a10.x * omwx + a11.x * wx; ra.x = t * omwy + b * wy;
                t = a00.y * omwx + a01.y * wx; b = a10.y * omwx + a11.y * wx; ra.y = t * omwy + b * wy;
                t = a00.z * omwx + a01.z * wx; b = a10.z * omwx + a11.z * wx; ra.z = t * omwy + b * wy;
                t = a00.w * omwx + a01.w * wx; b = a10.w * omwx + a11.w * wx; ra.w = t * omwy + b * wy;

                t = b00.x * omwx + b01.x * wx; b = b10.x * omwx + b11.x * wx; rb.x = t * omwy + b * wy;
                t = b00.y * omwx + b01.y * wx; b = b10.y * omwx + b11.y * wx; rb.y = t * omwy + b * wy;
                t = b00.z * omwx + b01.z * wx; b = b10.z * omwx + b11.z * wx; rb.z = t * omwy + b * wy;
                t = b00.w * omwx + b01.w * wx; b = b10.w * omwx + b11.w * wx; rb.w = t * omwy + b * wy;
            }
            *oa = ra;
            *obp = rb;
        }
    }
#undef LD4
}

extern "C" void kernel_launch(void* const* d_in, const int* in_sizes, int n_in,
                              void* d_out, int out_size) {
    const float* img  = (const float*)d_in[0];
    const float* rois = (const float*)d_in[1];
    float* out = (float*)d_out;

    const int n_rois = in_sizes[1] / 4;
    const int pp = out_size / (n_rois * IMG_C);
    int ps = (int)(sqrtf((float)pp) + 0.5f);
    if (ps < 1) ps = 1;
    if (ps * ps > MAX_PP) ps = 8;

    roipool_kernel<<<n_rois, 256>>>(img, rois, out, ps);
}